// round 3
// baseline (speedup 1.0000x reference)
#include <cuda_runtime.h>
#include <math.h>
#include <stdint.h>

// Problem constants
#define BB    256      // batch
#define FF    256      // frames (sequential)
#define NJ3C  51       // NJ*3
#define INDIM 34
#define DD    512      // hidden
#define G4    2048     // 4*D gates
#define APKS  576      // packed A row stride: [pred(51) | h0(512) | pad]
#define KA    597      // 51 + 512 + 34 (pred | h0 | x)
#define KAP   608      // KA padded to multiple of 16
#define KB    1024     // h0n(512) | h1(512)

typedef unsigned long long ull;

// ---------------- device scratch (static, no allocation) ----------------
__device__ float d_Apk[2][BB][APKS];     // [pred | h0] double buffered
__device__ float d_h1b[2][BB][DD];       // h1 double buffered
__device__ float d_c0s[BB][DD];          // c0
__device__ float d_c1s[BB][DD];          // c1
__device__ float d_Wpk0[KAP][G4];        // packed LSTM0 weights, k-major, n=d*4+gate
__device__ float d_cb[G4];               // embed_b@Wih0x + bih0 + bhh0 (gate-interleaved)
__device__ float d_Wpk1[KB][G4];         // packed LSTM1 weights, k-major
__device__ float d_b1g[G4];              // bih1 + bhh1 (gate-interleaved)
__device__ float d_t1[BB][DD];           // init-MLP scratch
__device__ float d_t2[BB][1024];
__device__ float d_z[BB][G4];

__device__ __forceinline__ float sigm(float x){ return 1.0f/(1.0f+expf(-x)); }

// ---------------- packed f32x2 helpers (Blackwell FFMA2 path) ----------------
#define PACK2(d, x) asm("mov.b64 %0, {%1, %1};" : "=l"(d) : "r"(__float_as_uint(x)))
#define FMA2(d, a, b) asm("fma.rn.f32x2 %0, %1, %2, %0;" : "+l"(d) : "l"(a), "l"(b))
__device__ __forceinline__ void unpack2(ull v, float& lo, float& hi){
  unsigned ulo, uhi;
  asm("mov.b64 {%0, %1}, %2;" : "=r"(ulo), "=r"(uhi) : "l"(v));
  lo = __uint_as_float(ulo); hi = __uint_as_float(uhi);
}

// ---------------- setup: pack LSTM0 weights + fold embedding ----------------
// n = d*4 + g maps to reference gate row j = g*512 + d
// k layout: [0,51)   -> Wih0[:, 512+k]  (pred part)
//           [51,563) -> Whh0            (h0 part)
//           [563,597)-> Wc = embed_W @ Wih0[:, :512]^T  (x folded through embedding)
//           [597,608)-> 0
__global__ void pack0_kernel(const float* __restrict__ Wih0, const float* __restrict__ Whh0,
                             const float* __restrict__ embW, const float* __restrict__ embB,
                             const float* __restrict__ bih0, const float* __restrict__ bhh0){
  int n = blockIdx.x;
  int j = (n & 3) * DD + (n >> 2);
  __shared__ float row[DD];
  for (int k = threadIdx.x; k < DD; k += 64) row[k] = Wih0[j*563 + k];
  __syncthreads();
  for (int k = threadIdx.x; k < KAP; k += 64){
    float w;
    if (k < NJ3C)      w = Wih0[j*563 + DD + k];
    else if (k < 563)  w = Whh0[j*DD + (k - NJ3C)];
    else if (k < KA){
      int i = k - 563;
      const float* er = embW + i*DD;
      float s = 0.f;
      for (int kk = 0; kk < DD; kk++) s = fmaf(er[kk], row[kk], s);
      w = s;
    } else w = 0.f;
    d_Wpk0[k][n] = w;
  }
  if (threadIdx.x == 0){
    float s = 0.f;
    for (int kk = 0; kk < DD; kk++) s = fmaf(embB[kk], row[kk], s);
    d_cb[n] = s + bih0[j] + bhh0[j];
  }
}

__global__ void pack1_kernel(const float* __restrict__ Wih1, const float* __restrict__ Whh1,
                             const float* __restrict__ bih1, const float* __restrict__ bhh1){
  int idx = blockIdx.x * 256 + threadIdx.x;   // KB * G4 total
  int k = idx >> 11;
  int n = idx & (G4 - 1);
  int j = (n & 3) * DD + (n >> 2);
  d_Wpk1[k][n] = (k < DD) ? Wih1[j*DD + k] : Whh1[j*DD + (k - DD)];
  if (k == 0) d_b1g[n] = bih1[j] + bhh1[j];
}

// ---------------- 16-deep packed-FMA microtile core ----------------
// acc2[p][j]: packed rows (m0+2p, m0+2p+1) for column n0+j. lo lane = even row.
__device__ __forceinline__ void mm16p(const float (*As)[68], const float (*Ws)[64],
                                      ull acc2[2][4], int m0, int n0){
#pragma unroll
  for (int kk = 0; kk < 16; kk++){
    ulonglong2 aa = *reinterpret_cast<const ulonglong2*>(&As[kk][m0]);  // (a0,a1),(a2,a3)
    float4 b4 = *reinterpret_cast<const float4*>(&Ws[kk][n0]);
    ull b0, b1, b2, b3;
    PACK2(b0, b4.x); PACK2(b1, b4.y); PACK2(b2, b4.z); PACK2(b3, b4.w);
    FMA2(acc2[0][0], aa.x, b0); FMA2(acc2[0][1], aa.x, b1);
    FMA2(acc2[0][2], aa.x, b2); FMA2(acc2[0][3], aa.x, b3);
    FMA2(acc2[1][0], aa.y, b0); FMA2(acc2[1][1], aa.y, b1);
    FMA2(acc2[1][2], aa.y, b2); FMA2(acc2[1][3], aa.y, b3);
  }
}

// ---------------- generic tiled GEMM with device-side buffer selection ----------------
// a_sel: 0 = external pointer, 1 = d_t1, 2 = d_t2
// c_sel: 1 = d_t1, 2 = d_t2, 3 = d_z
__global__ __launch_bounds__(256)
void gemm_bias_act(const float* __restrict__ Aext, int a_sel, int lda,
                   const float* __restrict__ W, int N, int K,
                   const float* __restrict__ bias, int c_sel, int relu){
  const float* A = (a_sel == 0) ? Aext : (a_sel == 1 ? &d_t1[0][0] : &d_t2[0][0]);
  float* C = (c_sel == 1) ? &d_t1[0][0] : (c_sel == 2 ? &d_t2[0][0] : &d_z[0][0]);
  __shared__ __align__(16) float As[16][68];
  __shared__ __align__(16) float Ws[16][64];
  int tid = threadIdx.x;
  int tx = tid & 15, ty = tid >> 4;
  int nb = blockIdx.x * 64, mb = blockIdx.y * 64;
  int m0 = ty * 4, n0 = tx * 4;
  ull acc2[2][4];
#pragma unroll
  for (int j2 = 0; j2 < 4; j2++){
    float bv = bias[nb + n0 + j2];
    PACK2(acc2[0][j2], bv);
    acc2[1][j2] = acc2[0][j2];
  }
  int r  = tid >> 2, kq = (tid & 3) * 4;   // A loader
  int wk = tid >> 4, wn = (tid & 15) * 4;  // W loader
  for (int k0 = 0; k0 < K; k0 += 16){
#pragma unroll
    for (int i = 0; i < 4; i++){
      int k = k0 + kq + i;
      As[kq+i][r] = (k < K) ? A[(size_t)(mb + r) * lda + k] : 0.f;
    }
    {
      int k = k0 + wk;
      float4 v = make_float4(0.f,0.f,0.f,0.f);
      if (k < K) v = *reinterpret_cast<const float4*>(W + (size_t)k * N + nb + wn);
      *reinterpret_cast<float4*>(&Ws[wk][wn]) = v;
    }
    __syncthreads();
    mm16p(As, Ws, acc2, m0, n0);
    __syncthreads();
  }
#pragma unroll
  for (int p = 0; p < 2; p++)
#pragma unroll
    for (int j2 = 0; j2 < 4; j2++){
      float lo, hi; unpack2(acc2[p][j2], lo, hi);
      if (relu){ lo = fmaxf(lo, 0.f); hi = fmaxf(hi, 0.f); }
      C[(size_t)(mb + m0 + 2*p    ) * N + nb + n0 + j2] = lo;
      C[(size_t)(mb + m0 + 2*p + 1) * N + nb + n0 + j2] = hi;
    }
}

// ---------------- scatter init MLP output into h/c state + pred0 ----------------
__global__ void init_state_kernel(const float* __restrict__ init){
  int idx = blockIdx.x * 256 + threadIdx.x;   // BB * 2112
  int b = idx / 2112, r2 = idx % 2112;
  if (b >= BB) return;
  if (r2 < 2048){
    float v = d_z[b][r2];
    if      (r2 < 512)  d_Apk[0][b][NJ3C + r2] = v;         // h layer0
    else if (r2 < 1024) d_h1b[0][b][r2 - 512] = v;          // h layer1
    else if (r2 < 1536) d_c0s[b][r2 - 1024] = v;            // c layer0
    else                d_c1s[b][r2 - 1536] = v;            // c layer1
  } else {
    int p = r2 - 2048;
    if (p < NJ3C) d_Apk[0][b][p] = init[b * 85 + p];        // pred0 = init[:, :51]
  }
}

// ---------------- LSTM epilogue helper: one packed acc row-pair -> gates ----------------
__device__ __forceinline__ void lstm_epilogue_pair(ull a0, ull a1, ull a2, ull a3,
                                                   int b_even, int d,
                                                   float (*cs)[DD],
                                                   float* hout_even, float* hout_odd){
  float i_lo, i_hi, f_lo, f_hi, g_lo, g_hi, o_lo, o_hi;
  unpack2(a0, i_lo, i_hi); unpack2(a1, f_lo, f_hi);
  unpack2(a2, g_lo, g_hi); unpack2(a3, o_lo, o_hi);
  {
    float ig = sigm(i_lo), fg = sigm(f_lo), gg = tanhf(g_lo), og = sigm(o_lo);
    float cn = fmaf(fg, cs[b_even][d], ig * gg);
    cs[b_even][d] = cn;
    *hout_even = og * tanhf(cn);
  }
  {
    float ig = sigm(i_hi), fg = sigm(f_hi), gg = tanhf(g_hi), og = sigm(o_hi);
    float cn = fmaf(fg, cs[b_even + 1][d], ig * gg);
    cs[b_even + 1][d] = cn;
    *hout_odd = og * tanhf(cn);
  }
}

// ---------------- per-step LSTM layer 0 (fused GEMM + pointwise) ----------------
__global__ __launch_bounds__(256)
void lstm0_kernel(const float* __restrict__ x, int t, int cur){
  const float* Apk  = &d_Apk[cur][0][0];
  float*       ApkN = &d_Apk[cur ^ 1][0][0];
  __shared__ __align__(16) float As[16][68];
  __shared__ __align__(16) float Ws[16][64];
  int tid = threadIdx.x;
  int tx = tid & 15, ty = tid >> 4;
  int nb = blockIdx.x * 64, mb = blockIdx.y * 64;
  int m0 = ty * 4, n0 = tx * 4;
  ull acc2[2][4];
#pragma unroll
  for (int j2 = 0; j2 < 4; j2++){
    float bv = d_cb[nb + n0 + j2];
    PACK2(acc2[0][j2], bv);
    acc2[1][j2] = acc2[0][j2];
  }
  int r  = tid >> 2, kq = (tid & 3) * 4;
  int wk = tid >> 4, wn = (tid & 15) * 4;
  for (int k0 = 0; k0 < KAP; k0 += 16){
#pragma unroll
    for (int i = 0; i < 4; i++){
      int k = k0 + kq + i;
      int b = mb + r;
      float v;
      if (k < 563)      v = Apk[(size_t)b * APKS + k];                       // pred | h0
      else if (k < KA)  v = x[(size_t)(b * FF + t) * INDIM + (k - 563)];     // x (folded Wc)
      else              v = 0.f;
      As[kq+i][r] = v;
    }
    *reinterpret_cast<float4*>(&Ws[wk][wn]) =
        *reinterpret_cast<const float4*>(&d_Wpk0[k0 + wk][nb + wn]);
    __syncthreads();
    mm16p(As, Ws, acc2, m0, n0);
    __syncthreads();
  }
  int d = (nb + n0) >> 2;   // one thread owns all 4 gates of (b, d)
#pragma unroll
  for (int p = 0; p < 2; p++){
    int b = mb + m0 + 2*p;
    float he, ho;
    lstm_epilogue_pair(acc2[p][0], acc2[p][1], acc2[p][2], acc2[p][3],
                       b, d, d_c0s, &he, &ho);
    ApkN[(size_t)b       * APKS + NJ3C + d] = he;   // h0n even row
    ApkN[(size_t)(b + 1) * APKS + NJ3C + d] = ho;   // h0n odd row
  }
}

// ---------------- per-step LSTM layer 1 (fused GEMM + pointwise + ctx output) ----------------
__global__ __launch_bounds__(256)
void lstm1_kernel(float* __restrict__ out2, int t, int cur){
  const float* ApkN = &d_Apk[cur ^ 1][0][0];   // h0n at [51..563)
  const float* h1c  = &d_h1b[cur][0][0];
  float*       h1n  = &d_h1b[cur ^ 1][0][0];
  __shared__ __align__(16) float As[16][68];
  __shared__ __align__(16) float Ws[16][64];
  int tid = threadIdx.x;
  int tx = tid & 15, ty = tid >> 4;
  int nb = blockIdx.x * 64, mb = blockIdx.y * 64;
  int m0 = ty * 4, n0 = tx * 4;
  ull acc2[2][4];
#pragma unroll
  for (int j2 = 0; j2 < 4; j2++){
    float bv = d_b1g[nb + n0 + j2];
    PACK2(acc2[0][j2], bv);
    acc2[1][j2] = acc2[0][j2];
  }
  int r  = tid >> 2, kq = (tid & 3) * 4;
  int wk = tid >> 4, wn = (tid & 15) * 4;
  for (int k0 = 0; k0 < KB; k0 += 16){
#pragma unroll
    for (int i = 0; i < 4; i++){
      int k = k0 + kq + i;
      int b = mb + r;
      float v = (k < DD) ? ApkN[(size_t)b * APKS + NJ3C + k]
                         : h1c[(size_t)b * DD + (k - DD)];
      As[kq+i][r] = v;
    }
    *reinterpret_cast<float4*>(&Ws[wk][wn]) =
        *reinterpret_cast<const float4*>(&d_Wpk1[k0 + wk][nb + wn]);
    __syncthreads();
    mm16p(As, Ws, acc2, m0, n0);
    __syncthreads();
  }
  int d = (nb + n0) >> 2;
#pragma unroll
  for (int p = 0; p < 2; p++){
    int b = mb + m0 + 2*p;
    float he, ho;
    lstm_epilogue_pair(acc2[p][0], acc2[p][1], acc2[p][2], acc2[p][3],
                       b, d, d_c1s, &he, &ho);
    h1n[(size_t)b       * DD + d] = he;
    h1n[(size_t)(b + 1) * DD + d] = ho;
    out2[((size_t)b       * FF + t) * 563 + d] = he;   // motion_context[:, t, 0:512]
    out2[((size_t)(b + 1) * FF + t) * 563 + d] = ho;
  }
}

// ---------------- per-step decoder: pred = h1n @ dec_W + dec_b ----------------
__global__ void dec_kernel(const float* __restrict__ decW, const float* __restrict__ decB,
                           float* __restrict__ out1, float* __restrict__ out2, int t, int cur){
  int b = blockIdx.x;
  int tid = threadIdx.x;                 // 512 threads
  int p = tid & 63, seg = tid >> 6;      // 8 segments x 64 k
  __shared__ float red[8][64];
  const float* h = &d_h1b[cur ^ 1][b][0];
  float s = 0.f;
  if (p < NJ3C){
    int kb = seg * 64;
#pragma unroll 8
    for (int k = 0; k < 64; k++) s = fmaf(h[kb + k], decW[(kb + k) * NJ3C + p], s);
  }
  red[seg][p] = s;
  __syncthreads();
  if (tid < 64 && p < NJ3C){
    float v = decB[p];
#pragma unroll
    for (int q = 0; q < 8; q++) v += red[q][p];
    d_Apk[cur ^ 1][b][p] = v;                               // pred for next step
    out1[((size_t)b * FF + t) * NJ3C + p] = v;              // pred_kp3d
    out2[((size_t)b * FF + t) * 563 + 512 + p] = v;         // motion_context[:, t, 512:563]
  }
}

// ---------------- launch: kernel launches ONLY (graph-capture safe) ----------------
extern "C" void kernel_launch(void* const* d_in, const int* in_sizes, int n_in,
                              void* d_out, int out_size){
  const float* x     = (const float*)d_in[0];
  const float* initp = (const float*)d_in[1];
  const float* embW  = (const float*)d_in[2];
  const float* embB  = (const float*)d_in[3];
  const float* niW1  = (const float*)d_in[4];
  const float* nib1  = (const float*)d_in[5];
  const float* niW2  = (const float*)d_in[6];
  const float* nib2  = (const float*)d_in[7];
  const float* niW3  = (const float*)d_in[8];
  const float* nib3  = (const float*)d_in[9];
  const float* Wih0  = (const float*)d_in[10];
  const float* Whh0  = (const float*)d_in[11];
  const float* bih0  = (const float*)d_in[12];
  const float* bhh0  = (const float*)d_in[13];
  const float* Wih1  = (const float*)d_in[14];
  const float* Whh1  = (const float*)d_in[15];
  const float* bih1  = (const float*)d_in[16];
  const float* bhh1  = (const float*)d_in[17];
  const float* decW  = (const float*)d_in[18];
  const float* decB  = (const float*)d_in[19];

  float* out  = (float*)d_out;
  float* out1 = out;                                   // pred_kp3d [B,F,17,3]
  float* out2 = out + (size_t)BB * FF * NJ3C;          // motion_context [B,F,563]

  // weight packing (recomputed every call; deterministic)
  pack0_kernel<<<G4, 64>>>(Wih0, Whh0, embW, embB, bih0, bhh0);
  pack1_kernel<<<(KB * G4) / 256, 256>>>(Wih1, Whh1, bih1, bhh1);

  // init MLP: 85 -> 512 -> 1024 -> 2048, then scatter into h/c + pred0
  gemm_bias_act<<<dim3(DD/64,   BB/64), 256>>>(initp, 0, 85,    niW1, DD,   85,   nib1, 1, 1);
  gemm_bias_act<<<dim3(1024/64, BB/64), 256>>>(nullptr, 1, DD,  niW2, 1024, DD,   nib2, 2, 1);
  gemm_bias_act<<<dim3(G4/64,   BB/64), 256>>>(nullptr, 2, 1024, niW3, G4,  1024, nib3, 3, 0);
  init_state_kernel<<<2112, 256>>>(initp);

  // sequential recurrence: 256 steps x (LSTM0, LSTM1, dec)
  for (int t = 0; t < FF; t++){
    int cur = t & 1;
    lstm0_kernel<<<dim3(G4/64, BB/64), 256>>>(x, t, cur);
    lstm1_kernel<<<dim3(G4/64, BB/64), 256>>>(out2, t, cur);
    dec_kernel<<<BB, 512>>>(decW, decB, out1, out2, t, cur);
  }
}